// round 5
// baseline (speedup 1.0000x reference)
#include <cuda_runtime.h>
#include <cuda_bf16.h>

// activation (N=32, C=16, H=224, W=224) fp32.
// c0-1 identity, c2-3 1x1 relu, c4-7 2x2, c8-11 4x4, c12-15 3x3.
#define HW4 12544   // float4 per image-channel
#define W4  56      // float4 per row
#define H_  224
#define Q8  1568    // HW4/8

// Per-image thread units (heavy-first). Light paths: 8 float4 per thread.
//   [0,     5700) : 3x3 units   (4ch * 1425, 9 f4)
//   [5700, 11972) : 4x4 units   (4ch * 1568: 4 rows x 2 f4, 2 masks)
//   [11972,18244) : 2x2 units   (4ch * 1568: 4 rows x 2 f4, 8 masks)
//   [18244,24516) : elementwise (4ch * 1568: 8 strided f4)
#define SEG_C 5700
#define SEG_B 11972
#define SEG_A 18244
#define PER_N 24516
#define TOTAL (32 * PER_N)   // 784,512

__device__ __forceinline__ float4 ldcs4(const float4* p) {
    return __ldcs(p);
}

__global__ __launch_bounds__(256) void block_relu_fused(
    const float4* __restrict__ in, float4* __restrict__ out)
{
    int i = blockIdx.x * 256 + threadIdx.x;
    if (i >= TOTAL) return;
    int n = i / PER_N;
    int u = i - n * PER_N;
    const size_t nbase = (size_t)n * 16 * HW4;

    if (u >= SEG_A) {
        // ---- c0-3: identity / elementwise relu, 8 strided float4 ----
        int t   = u - SEG_A;
        int c   = t / Q8;
        int off = t - c * Q8;
        size_t g = nbase + (size_t)c * HW4 + off;
        float4 v[8];
        #pragma unroll
        for (int j = 0; j < 8; j++) v[j] = ldcs4(in + g + (size_t)j * Q8);
        if (c >= 2) {
            #pragma unroll
            for (int j = 0; j < 8; j++) {
                v[j].x = fmaxf(v[j].x, 0.f); v[j].y = fmaxf(v[j].y, 0.f);
                v[j].z = fmaxf(v[j].z, 0.f); v[j].w = fmaxf(v[j].w, 0.f);
            }
        }
        #pragma unroll
        for (int j = 0; j < 8; j++) out[g + (size_t)j * Q8] = v[j];
    } else if (u >= SEG_C) {
        // ---- c4-11: 4 rows x 2 float4 per thread ----
        bool is2x2 = (u >= SEG_B);
        int t  = u - (is2x2 ? SEG_B : SEG_C);
        int c  = (is2x2 ? 4 : 8) + t / Q8;
        int v  = t % Q8;
        int rq = v / 28;                   // 4-row group 0..55
        int fp = v - rq * 28;              // f4-pair 0..27
        size_t i0 = nbase + (size_t)c * HW4 + (size_t)(4 * rq) * W4 + 2 * fp;

        float4 r[4][2];
        #pragma unroll
        for (int j = 0; j < 4; j++) {
            r[j][0] = ldcs4(in + i0 + (size_t)j * W4);
            r[j][1] = ldcs4(in + i0 + (size_t)j * W4 + 1);
        }

        if (is2x2) {
            #pragma unroll
            for (int k = 0; k < 2; k++) {
                // top block-row (rows 0-1), bottom (rows 2-3); left pair xy, right zw
                float tx = r[0][k].x + r[1][k].x, ty = r[0][k].y + r[1][k].y;
                float tz = r[0][k].z + r[1][k].z, tw = r[0][k].w + r[1][k].w;
                float bx = r[2][k].x + r[3][k].x, by = r[2][k].y + r[3][k].y;
                float bz = r[2][k].z + r[3][k].z, bw = r[2][k].w + r[3][k].w;
                float mTL = ((tx + ty) >= 0.f) ? 1.f : 0.f;
                float mTR = ((tz + tw) >= 0.f) ? 1.f : 0.f;
                float mBL = ((bx + by) >= 0.f) ? 1.f : 0.f;
                float mBR = ((bz + bw) >= 0.f) ? 1.f : 0.f;
                r[0][k].x *= mTL; r[0][k].y *= mTL; r[0][k].z *= mTR; r[0][k].w *= mTR;
                r[1][k].x *= mTL; r[1][k].y *= mTL; r[1][k].z *= mTR; r[1][k].w *= mTR;
                r[2][k].x *= mBL; r[2][k].y *= mBL; r[2][k].z *= mBR; r[2][k].w *= mBR;
                r[3][k].x *= mBL; r[3][k].y *= mBL; r[3][k].z *= mBR; r[3][k].w *= mBR;
            }
        } else {
            #pragma unroll
            for (int k = 0; k < 2; k++) {
                float cs0 = r[0][k].x + r[1][k].x + r[2][k].x + r[3][k].x;
                float cs1 = r[0][k].y + r[1][k].y + r[2][k].y + r[3][k].y;
                float cs2 = r[0][k].z + r[1][k].z + r[2][k].z + r[3][k].z;
                float cs3 = r[0][k].w + r[1][k].w + r[2][k].w + r[3][k].w;
                float m = ((cs0 + cs1 + cs2 + cs3) >= 0.f) ? 1.f : 0.f;
                #pragma unroll
                for (int j = 0; j < 4; j++) {
                    r[j][k].x *= m; r[j][k].y *= m; r[j][k].z *= m; r[j][k].w *= m;
                }
            }
        }
        #pragma unroll
        for (int j = 0; j < 4; j++) {
            out[i0 + (size_t)j * W4]     = r[j][0];
            out[i0 + (size_t)j * W4 + 1] = r[j][1];
        }
    } else {
        // ---- c12-15: 3x3 blocks, four blocks per thread (3 rows x 12 cols) ----
        int c  = 12 + u / 1425;
        int v  = u % 1425;
        int br = v / 19;              // block-row 0..74
        int s  = v - br * 19;         // 12-col strip 0..18
        int r0 = br * 3;
        size_t base = nbase + (size_t)c * HW4;

        float4 val[3][3];
        #pragma unroll
        for (int r = 0; r < 3; r++) {
            int rr = r0 + r;
            bool rv = rr < H_;
            #pragma unroll
            for (int k = 0; k < 3; k++) {
                int fc = s * 3 + k;
                if (rv && fc < W4)
                    val[r][k] = ldcs4(in + base + (size_t)rr * W4 + fc);
                else
                    val[r][k] = make_float4(0.f, 0.f, 0.f, 0.f);
            }
        }

        float cs[12];
        #pragma unroll
        for (int k = 0; k < 3; k++) {
            cs[4 * k + 0] = val[0][k].x + val[1][k].x + val[2][k].x;
            cs[4 * k + 1] = val[0][k].y + val[1][k].y + val[2][k].y;
            cs[4 * k + 2] = val[0][k].z + val[1][k].z + val[2][k].z;
            cs[4 * k + 3] = val[0][k].w + val[1][k].w + val[2][k].w;
        }
        float m[4];
        #pragma unroll
        for (int g = 0; g < 4; g++)
            m[g] = ((cs[3 * g] + cs[3 * g + 1] + cs[3 * g + 2]) >= 0.f) ? 1.f : 0.f;

        #pragma unroll
        for (int r = 0; r < 3; r++) {
            int rr = r0 + r;
            if (rr >= H_) break;
            #pragma unroll
            for (int k = 0; k < 3; k++) {
                int fc = s * 3 + k;
                if (fc < W4) {
                    float4 tv = val[r][k];
                    int L = 4 * k;
                    tv.x *= m[(L + 0) / 3];
                    tv.y *= m[(L + 1) / 3];
                    tv.z *= m[(L + 2) / 3];
                    tv.w *= m[(L + 3) / 3];
                    out[base + (size_t)rr * W4 + fc] = tv;
                }
            }
        }
    }
}

extern "C" void kernel_launch(void* const* d_in, const int* in_sizes, int n_in,
                              void* d_out, int out_size)
{
    const float4* in  = (const float4*)d_in[0];
    float4*       out = (float4*)d_out;
    block_relu_fused<<<(TOTAL + 255) / 256, 256>>>(in, out);  // 3065 CTAs
}